// round 11
// baseline (speedup 1.0000x reference)
#include <cuda_runtime.h>
#include <cstdint>

// ContrastiveLoss: B=16384, D=256
// loss = -(1/B) * sum_b [ dot(Tn_b,Sn_b) - log( sum_{c: lab_c != lab_b} exp(Tn_b . Sn_c) ) ]
// R11: int8 mma.sync, CORRECT full-K=256 single chunk. TM=128 x TN=64 tile,
// A(32KB)+B(16KB) = 48KB static SMEM exactly, XOR-swizzled (no pad), cp.async
// loads, labels/scales from gmem in epilogue, shfl-only reduction.

#define NB 16384
#define D 256
#define TM 128
#define TN 64
#define CTILES (NB / TN)    // 256 col tiles
#define NPW (CTILES * 2)    // negpart width: 2 wx partials per col tile

// -------- scratch (device globals: no allocation allowed) --------
__device__ signed char g_Tq[(size_t)NB * D];        // 4 MB (int8)
__device__ signed char g_Sq[(size_t)NB * D];        // 4 MB
__device__ float g_scT[NB];                         // rowscale_T * log2(e)
__device__ float g_scS[NB];                         // rowscale_S
__device__ float g_diag[NB];
__device__ int   g_lab[NB];
__device__ float g_negpart[(size_t)NB * NPW];       // 32 MB
__device__ float g_partial[64];

__device__ __forceinline__ uint32_t smem_u32(const void* p) {
    uint32_t a;
    asm("{ .reg .u64 t; cvta.to.shared.u64 t, %1; cvt.u32.u64 %0, t; }" : "=r"(a) : "l"(p));
    return a;
}
__device__ __forceinline__ void ldm_x4(uint32_t& r0, uint32_t& r1, uint32_t& r2, uint32_t& r3,
                                       uint32_t addr) {
    asm volatile("ldmatrix.sync.aligned.m8n8.x4.shared.b16 {%0,%1,%2,%3}, [%4];"
                 : "=r"(r0), "=r"(r1), "=r"(r2), "=r"(r3) : "r"(addr));
}
__device__ __forceinline__ void mma_s8(int* d, const uint32_t* a, uint32_t b0, uint32_t b1) {
    asm volatile(
        "mma.sync.aligned.m16n8k32.row.col.s32.s8.s8.s32 "
        "{%0,%1,%2,%3}, {%4,%5,%6,%7}, {%8,%9}, {%0,%1,%2,%3};"
        : "+r"(d[0]), "+r"(d[1]), "+r"(d[2]), "+r"(d[3])
        : "r"(a[0]), "r"(a[1]), "r"(a[2]), "r"(a[3]), "r"(b0), "r"(b1));
}
__device__ __forceinline__ float ex2f(float x) {
    float y;
    asm("ex2.approx.f32 %0, %1;" : "=f"(y) : "f"(x));
    return y;
}
__device__ __forceinline__ void cp16(uint32_t dst, const void* src) {
    asm volatile("cp.async.cg.shared.global [%0], [%1], 16;" :: "r"(dst), "l"(src));
}

// ---------------------------------------------------------------
// Kernel 1: normalize rows, int8 quantize with per-row scale, diag, labels.
// ---------------------------------------------------------------
__global__ void k_norm(const float* __restrict__ T,
                       const float* __restrict__ S,
                       const int* __restrict__ lab) {
    int row = blockIdx.x;
    int tid = threadIdx.x;
    size_t base = (size_t)row * D + tid;
    float t = T[base];
    float s = S[base];
    float tt = t * t, ss = s * s, ts = t * s;
    #pragma unroll
    for (int o = 16; o; o >>= 1) {
        tt += __shfl_xor_sync(0xffffffffu, tt, o);
        ss += __shfl_xor_sync(0xffffffffu, ss, o);
        ts += __shfl_xor_sync(0xffffffffu, ts, o);
    }
    __shared__ float stt[8], sss[8], sts[8], smt[8], sms[8];
    int w = tid >> 5;
    if ((tid & 31) == 0) { stt[w] = tt; sss[w] = ss; sts[w] = ts; }
    __syncthreads();
    float TT = 0.f, SS = 0.f, TS = 0.f;
    #pragma unroll
    for (int i = 0; i < 8; i++) { TT += stt[i]; SS += sss[i]; TS += sts[i]; }
    float nT = fmaxf(sqrtf(TT), 1e-8f);
    float nS = fmaxf(sqrtf(SS), 1e-8f);
    float vT = t / nT;
    float vS = s / nS;

    float mT = fabsf(vT), mS = fabsf(vS);
    #pragma unroll
    for (int o = 16; o; o >>= 1) {
        mT = fmaxf(mT, __shfl_xor_sync(0xffffffffu, mT, o));
        mS = fmaxf(mS, __shfl_xor_sync(0xffffffffu, mS, o));
    }
    if ((tid & 31) == 0) { smt[w] = mT; sms[w] = mS; }
    __syncthreads();
    float MT = 1e-12f, MS = 1e-12f;
    #pragma unroll
    for (int i = 0; i < 8; i++) { MT = fmaxf(MT, smt[i]); MS = fmaxf(MS, sms[i]); }

    float qT = rintf(vT * (127.f / MT));
    float qS = rintf(vS * (127.f / MS));
    g_Tq[base] = (signed char)(int)fminf(fmaxf(qT, -127.f), 127.f);
    g_Sq[base] = (signed char)(int)fminf(fmaxf(qS, -127.f), 127.f);
    if (tid == 0) {
        g_scT[row] = (MT / 127.f) * 1.4426950408889634f;   // fold log2(e)
        g_scS[row] = (MS / 127.f);
        g_diag[row] = TS / (nT * nS);
        g_lab[row]  = lab[row];
    }
}

// ---------------------------------------------------------------
// Kernel 2: 128x64 tile GEMM via int8 mma.sync, full K=256 in one chunk.
// 256 threads = 8 warps (4 wy x 2 wx); warp tile 32x32 (2x4 m16n8k32 frags).
// SMEM rows: 256 B (16 granules of 16 B), swizzle: granule ^= (row & 7).
// ---------------------------------------------------------------
__global__ __launch_bounds__(256, 2) void k_gemm() {
    __shared__ unsigned char sA[TM * 256];   // 32768 B
    __shared__ unsigned char sB[TN * 256];   // 16384 B

    const int tid = threadIdx.x;
    const int l = tid & 31, w = tid >> 5;
    const int wy = w >> 1, wx = w & 1;
    const int rowBase = blockIdx.y * TM;
    const int colBase = blockIdx.x * TN;
    const uint32_t sAu = smem_u32(sA);
    const uint32_t sBu = smem_u32(sB);

    // ---- tile loads: cp.async 16B granules, swizzled dst ----
    {
        const char* srcA = (const char*)(g_Tq + (size_t)rowBase * D);
        const char* srcB = (const char*)(g_Sq + (size_t)colBase * D);
        #pragma unroll
        for (int i = 0; i < 8; i++) {               // A: 2048 granules
            int idx = i * 256 + tid;
            int r = idx >> 4, c = idx & 15;
            cp16(sAu + r * 256 + ((c ^ (r & 7)) << 4), srcA + (size_t)r * 256 + c * 16);
        }
        #pragma unroll
        for (int i = 0; i < 4; i++) {               // B: 1024 granules
            int idx = i * 256 + tid;
            int r = idx >> 4, c = idx & 15;
            cp16(sBu + r * 256 + ((c ^ (r & 7)) << 4), srcB + (size_t)r * 256 + c * 16);
        }
        asm volatile("cp.async.commit_group;" ::: "memory");
    }

    // per-lane constant parts of the swizzled ldmatrix addresses
    // A: row = wy*32 + mi*16 + (l & 15); granule = (ks*2 + (l>>4)) ^ (l & 7)
    // B: row = wx*32 + j*16 + ((l>>4)&1)*8 + (l & 7); granule = (ks*2 + ((l>>3)&1)) ^ (l & 7)
    const uint32_t aRow0 = sAu + (uint32_t)(wy * 32 + (l & 15)) * 256u;
    const uint32_t bRow0 = sBu + (uint32_t)(wx * 32 + ((l >> 4) & 1) * 8 + (l & 7)) * 256u;
    const int aGsel = (l >> 4);          // 0/1
    const int bGsel = ((l >> 3) & 1);    // 0/1
    const int lx7   = (l & 7);

    int acc[2][4][4];
    #pragma unroll
    for (int mi = 0; mi < 2; mi++)
        #pragma unroll
        for (int ni = 0; ni < 4; ni++)
            #pragma unroll
            for (int k = 0; k < 4; k++) acc[mi][ni][k] = 0;

    asm volatile("cp.async.wait_group 0;" ::: "memory");
    __syncthreads();

    // 8 k-steps of 32 int8 each, no intermediate syncs
    #pragma unroll
    for (int ks = 0; ks < 8; ks++) {
        const uint32_t aOff = (uint32_t)(((ks * 2 + aGsel) ^ lx7) << 4);
        const uint32_t bOff = (uint32_t)(((ks * 2 + bGsel) ^ lx7) << 4);
        uint32_t a[2][4], b[2][4];
        #pragma unroll
        for (int mi = 0; mi < 2; mi++)
            ldm_x4(a[mi][0], a[mi][1], a[mi][2], a[mi][3],
                   aRow0 + (uint32_t)(mi * 16 * 256) + aOff);
        #pragma unroll
        for (int j = 0; j < 2; j++)
            ldm_x4(b[j][0], b[j][1], b[j][2], b[j][3],
                   bRow0 + (uint32_t)(j * 16 * 256) + bOff);
        #pragma unroll
        for (int mi = 0; mi < 2; mi++)
            #pragma unroll
            for (int ni = 0; ni < 4; ni++)
                mma_s8(acc[mi][ni], a[mi],
                       b[ni >> 1][(ni & 1) * 2], b[ni >> 1][(ni & 1) * 2 + 1]);
    }

    // ---- epilogue: labels/scales from gmem, dequant + exp + mask + row sums ----
    int lr0[2], lr1[2];
    float sr0[2], sr1[2];
    #pragma unroll
    for (int mi = 0; mi < 2; mi++) {
        int r = rowBase + wy * 32 + mi * 16 + (l >> 2);
        lr0[mi] = __ldg(g_lab + r);     sr0[mi] = __ldg(g_scT + r);
        lr1[mi] = __ldg(g_lab + r + 8); sr1[mi] = __ldg(g_scT + r + 8);
    }
    int lc0[4], lc1[4];
    float sc0[4], sc1[4];
    #pragma unroll
    for (int ni = 0; ni < 4; ni++) {
        int c = colBase + wx * 32 + ni * 8 + (l & 3) * 2;
        lc0[ni] = __ldg(g_lab + c);     sc0[ni] = __ldg(g_scS + c);
        lc1[ni] = __ldg(g_lab + c + 1); sc1[ni] = __ldg(g_scS + c + 1);
    }

    float sLo[2], sHi[2];
    #pragma unroll
    for (int mi = 0; mi < 2; mi++) { sLo[mi] = 0.f; sHi[mi] = 0.f; }
    #pragma unroll
    for (int mi = 0; mi < 2; mi++)
        #pragma unroll
        for (int ni = 0; ni < 4; ni++) {
            float f00 = sr0[mi] * sc0[ni];
            float f01 = sr0[mi] * sc1[ni];
            float f10 = sr1[mi] * sc0[ni];
            float f11 = sr1[mi] * sc1[ni];
            float e0 = ex2f(__int2float_rn(acc[mi][ni][0]) * f00);
            float e1 = ex2f(__int2float_rn(acc[mi][ni][1]) * f01);
            float e2 = ex2f(__int2float_rn(acc[mi][ni][2]) * f10);
            float e3 = ex2f(__int2float_rn(acc[mi][ni][3]) * f11);
            sLo[mi] += (lr0[mi] != lc0[ni]) ? e0 : 0.f;
            sLo[mi] += (lr0[mi] != lc1[ni]) ? e1 : 0.f;
            sHi[mi] += (lr1[mi] != lc0[ni]) ? e2 : 0.f;
            sHi[mi] += (lr1[mi] != lc1[ni]) ? e3 : 0.f;
        }
    #pragma unroll
    for (int mi = 0; mi < 2; mi++) {
        sLo[mi] += __shfl_xor_sync(0xffffffffu, sLo[mi], 1);
        sLo[mi] += __shfl_xor_sync(0xffffffffu, sLo[mi], 2);
        sHi[mi] += __shfl_xor_sync(0xffffffffu, sHi[mi], 1);
        sHi[mi] += __shfl_xor_sync(0xffffffffu, sHi[mi], 2);
    }
    if ((l & 3) == 0) {
        int q = l >> 2;
        #pragma unroll
        for (int mi = 0; mi < 2; mi++) {
            int r0i = rowBase + wy * 32 + mi * 16 + q;
            g_negpart[(size_t)r0i * NPW + blockIdx.x * 2 + wx]       = sLo[mi];
            g_negpart[(size_t)(r0i + 8) * NPW + blockIdx.x * 2 + wx] = sHi[mi];
        }
    }
}

// ---------------------------------------------------------------
// Kernel 3: per-row finalize (sum NPW partials, diag - log) + block partials.
// ---------------------------------------------------------------
__global__ void k_rowfinal() {
    int idx = blockIdx.x * 256 + threadIdx.x;
    const float4* p = (const float4*)(g_negpart + (size_t)idx * NPW);
    float ns = 0.f;
    #pragma unroll 8
    for (int i = 0; i < NPW / 4; i++) {
        float4 v = p[i];
        ns += (v.x + v.y) + (v.z + v.w);
    }
    float val = g_diag[idx] - logf(ns);
    #pragma unroll
    for (int o = 16; o; o >>= 1) val += __shfl_xor_sync(0xffffffffu, val, o);
    __shared__ float sw[8];
    if ((threadIdx.x & 31) == 0) sw[threadIdx.x >> 5] = val;
    __syncthreads();
    if (threadIdx.x == 0) {
        float s = 0.f;
        #pragma unroll
        for (int i = 0; i < 8; i++) s += sw[i];
        g_partial[blockIdx.x] = s;
    }
}

// Kernel 4: final scalar
__global__ void k_final(float* __restrict__ out) {
    float v = g_partial[threadIdx.x];  // 64 threads
    #pragma unroll
    for (int o = 16; o; o >>= 1) v += __shfl_xor_sync(0xffffffffu, v, o);
    __shared__ float sw[2];
    if ((threadIdx.x & 31) == 0) sw[threadIdx.x >> 5] = v;
    __syncthreads();
    if (threadIdx.x == 0) out[0] = -(sw[0] + sw[1]) / (float)NB;
}

// ---------------------------------------------------------------
extern "C" void kernel_launch(void* const* d_in, const int* in_sizes, int n_in,
                              void* d_out, int out_size) {
    (void)in_sizes; (void)n_in; (void)out_size;
    const float* T   = (const float*)d_in[0];
    const float* S   = (const float*)d_in[1];
    const int*   lab = (const int*)d_in[2];
    float* out = (float*)d_out;

    k_norm<<<NB, 256>>>(T, S, lab);
    dim3 grid(CTILES, NB / TM);
    k_gemm<<<grid, 256>>>();
    k_rowfinal<<<64, 256>>>();
    k_final<<<1, 64>>>(out);
}

// round 13
// speedup vs baseline: 1.2573x; 1.2573x over previous
#include <cuda_runtime.h>
#include <cstdint>

// ContrastiveLoss: B=16384, D=256
// loss = -(1/B) * sum_b [ dot(Tn_b,Sn_b) - log( sum_{c: lab_c != lab_b} exp(Tn_b . Sn_c) ) ]
// R13: retry of R12 (infra failure). 128x128 int8 IMMA tile + 4x(K=64)
// double-buffered cp.async pipeline. 64B SMEM rows, XOR swizzle
// (r&3)^((r>>2)&1) -> conflict-free ldmatrix, no pad.

#define NB 16384
#define D 256
#define TM 128
#define TN 128
#define CT (NB / TN)        // 128 col tiles

// -------- scratch (device globals: no allocation allowed) --------
__device__ signed char g_Tq[(size_t)NB * D];        // 4 MB (int8)
__device__ signed char g_Sq[(size_t)NB * D];        // 4 MB
__device__ float g_scT[NB];                         // rowscale_T * log2(e)
__device__ float g_scS[NB];                         // rowscale_S
__device__ float g_diag[NB];
__device__ int   g_lab[NB];
__device__ float g_negpart[(size_t)NB * CT];        // 8 MB
__device__ float g_partial[64];

__device__ __forceinline__ uint32_t smem_u32(const void* p) {
    uint32_t a;
    asm("{ .reg .u64 t; cvta.to.shared.u64 t, %1; cvt.u32.u64 %0, t; }" : "=r"(a) : "l"(p));
    return a;
}
__device__ __forceinline__ void ldm_x4(uint32_t& r0, uint32_t& r1, uint32_t& r2, uint32_t& r3,
                                       uint32_t addr) {
    asm volatile("ldmatrix.sync.aligned.m8n8.x4.shared.b16 {%0,%1,%2,%3}, [%4];"
                 : "=r"(r0), "=r"(r1), "=r"(r2), "=r"(r3) : "r"(addr));
}
__device__ __forceinline__ void mma_s8(int* d, const uint32_t* a, uint32_t b0, uint32_t b1) {
    asm volatile(
        "mma.sync.aligned.m16n8k32.row.col.s32.s8.s8.s32 "
        "{%0,%1,%2,%3}, {%4,%5,%6,%7}, {%8,%9}, {%0,%1,%2,%3};"
        : "+r"(d[0]), "+r"(d[1]), "+r"(d[2]), "+r"(d[3])
        : "r"(a[0]), "r"(a[1]), "r"(a[2]), "r"(a[3]), "r"(b0), "r"(b1));
}
__device__ __forceinline__ float ex2f(float x) {
    float y;
    asm("ex2.approx.f32 %0, %1;" : "=f"(y) : "f"(x));
    return y;
}
__device__ __forceinline__ void cp16(uint32_t dst, const void* src) {
    asm volatile("cp.async.cg.shared.global [%0], [%1], 16;" :: "r"(dst), "l"(src));
}

// ---------------------------------------------------------------
// Kernel 1: normalize rows, int8 quantize with per-row scale, diag, labels.
// ---------------------------------------------------------------
__global__ void k_norm(const float* __restrict__ T,
                       const float* __restrict__ S,
                       const int* __restrict__ lab) {
    int row = blockIdx.x;
    int tid = threadIdx.x;
    size_t base = (size_t)row * D + tid;
    float t = T[base];
    float s = S[base];
    float tt = t * t, ss = s * s, ts = t * s;
    #pragma unroll
    for (int o = 16; o; o >>= 1) {
        tt += __shfl_xor_sync(0xffffffffu, tt, o);
        ss += __shfl_xor_sync(0xffffffffu, ss, o);
        ts += __shfl_xor_sync(0xffffffffu, ts, o);
    }
    __shared__ float stt[8], sss[8], sts[8], smt[8], sms[8];
    int w = tid >> 5;
    if ((tid & 31) == 0) { stt[w] = tt; sss[w] = ss; sts[w] = ts; }
    __syncthreads();
    float TT = 0.f, SS = 0.f, TS = 0.f;
    #pragma unroll
    for (int i = 0; i < 8; i++) { TT += stt[i]; SS += sss[i]; TS += sts[i]; }
    float nT = fmaxf(sqrtf(TT), 1e-8f);
    float nS = fmaxf(sqrtf(SS), 1e-8f);
    float vT = t / nT;
    float vS = s / nS;

    float mT = fabsf(vT), mS = fabsf(vS);
    #pragma unroll
    for (int o = 16; o; o >>= 1) {
        mT = fmaxf(mT, __shfl_xor_sync(0xffffffffu, mT, o));
        mS = fmaxf(mS, __shfl_xor_sync(0xffffffffu, mS, o));
    }
    if ((tid & 31) == 0) { smt[w] = mT; sms[w] = mS; }
    __syncthreads();
    float MT = 1e-12f, MS = 1e-12f;
    #pragma unroll
    for (int i = 0; i < 8; i++) { MT = fmaxf(MT, smt[i]); MS = fmaxf(MS, sms[i]); }

    float qT = rintf(vT * (127.f / MT));
    float qS = rintf(vS * (127.f / MS));
    g_Tq[base] = (signed char)(int)fminf(fmaxf(qT, -127.f), 127.f);
    g_Sq[base] = (signed char)(int)fminf(fmaxf(qS, -127.f), 127.f);
    if (tid == 0) {
        g_scT[row] = (MT / 127.f) * 1.4426950408889634f;   // fold log2(e)
        g_scS[row] = (MS / 127.f);
        g_diag[row] = TS / (nT * nS);
        g_lab[row]  = lab[row];
    }
}

// ---------------------------------------------------------------
// Kernel 2: 128x128 tile, 4 K-chunks of 64, 2-stage cp.async pipeline.
// 256 threads = 8 warps (2 wy x 4 wx); warp tile 64x32 (4x4 m16n8k32 frags).
// ---------------------------------------------------------------
__global__ __launch_bounds__(256, 2) void k_gemm() {
    __shared__ unsigned char sA[2][TM * 64];   // 16384 B
    __shared__ unsigned char sB[2][TN * 64];   // 16384 B
    __shared__ int   labR[128];
    __shared__ int   labC[128];
    __shared__ float scR[128];
    __shared__ float scC[128];
    __shared__ float red[4][128];

    const int tid = threadIdx.x;
    const int l = tid & 31, w = tid >> 5;
    const int wy = w >> 2, wx = w & 3;
    const int rowBase = blockIdx.y * TM;
    const int colBase = blockIdx.x * TN;
    const uint32_t sAu = smem_u32(sA);
    const uint32_t sBu = smem_u32(sB);

    const char* srcA = (const char*)(g_Tq + (size_t)rowBase * D);
    const char* srcB = (const char*)(g_Sq + (size_t)colBase * D);

    // chunk loader: 512 granules per matrix per chunk; 2 cp16/thread/matrix
    auto load_chunk = [&](int ck, int stage) {
        #pragma unroll
        for (int i = 0; i < 2; i++) {
            int idx = i * 256 + tid;
            int r = idx >> 2, c = idx & 3;
            int sw = (c ^ ((r & 3) ^ ((r >> 2) & 1))) << 4;
            cp16(sAu + stage * 8192 + r * 64 + sw, srcA + (size_t)r * 256 + ck * 64 + c * 16);
        }
        #pragma unroll
        for (int i = 0; i < 2; i++) {
            int idx = i * 256 + tid;
            int r = idx >> 2, c = idx & 3;
            int sw = (c ^ ((r & 3) ^ ((r >> 2) & 1))) << 4;
            cp16(sBu + stage * 8192 + r * 64 + sw, srcB + (size_t)r * 256 + ck * 64 + c * 16);
        }
        asm volatile("cp.async.commit_group;" ::: "memory");
    };

    load_chunk(0, 0);
    load_chunk(1, 1);

    if (tid < 128) {
        labR[tid] = g_lab[rowBase + tid];
        scR[tid]  = g_scT[rowBase + tid];
    } else {
        labC[tid - 128] = g_lab[colBase + tid - 128];
        scC[tid - 128]  = g_scS[colBase + tid - 128];
    }

    // lane-constant pieces of the swizzled ldmatrix addresses
    const int swzL = (l & 3) ^ ((l >> 2) & 1);
    const uint32_t aRowOff = (uint32_t)(wy * 64 + (l & 15)) * 64u;
    const uint32_t bRowOff = (uint32_t)(wx * 32 + ((l >> 4) & 1) * 8 + (l & 7)) * 64u;
    const int aGsel = (l >> 4);
    const int bGsel = ((l >> 3) & 1);

    int acc[4][4][4];
    #pragma unroll
    for (int mi = 0; mi < 4; mi++)
        #pragma unroll
        for (int ni = 0; ni < 4; ni++)
            #pragma unroll
            for (int k = 0; k < 4; k++) acc[mi][ni][k] = 0;

    #pragma unroll
    for (int ck = 0; ck < 4; ck++) {
        if (ck < 3) asm volatile("cp.async.wait_group 1;" ::: "memory");
        else        asm volatile("cp.async.wait_group 0;" ::: "memory");
        __syncthreads();

        const uint32_t aBase = sAu + (uint32_t)((ck & 1) * 8192) + aRowOff;
        const uint32_t bBase = sBu + (uint32_t)((ck & 1) * 8192) + bRowOff;

        #pragma unroll
        for (int ks = 0; ks < 2; ks++) {
            const uint32_t aOff = (uint32_t)(((ks * 2 + aGsel) ^ swzL) << 4);
            const uint32_t bOff = (uint32_t)(((ks * 2 + bGsel) ^ swzL) << 4);
            uint32_t a[4][4], b[2][4];
            #pragma unroll
            for (int mi = 0; mi < 4; mi++)
                ldm_x4(a[mi][0], a[mi][1], a[mi][2], a[mi][3],
                       aBase + (uint32_t)(mi * 1024) + aOff);
            #pragma unroll
            for (int j = 0; j < 2; j++)
                ldm_x4(b[j][0], b[j][1], b[j][2], b[j][3],
                       bBase + (uint32_t)(j * 1024) + bOff);
            #pragma unroll
            for (int mi = 0; mi < 4; mi++)
                #pragma unroll
                for (int ni = 0; ni < 4; ni++)
                    mma_s8(acc[mi][ni], a[mi],
                           b[ni >> 1][(ni & 1) * 2], b[ni >> 1][(ni & 1) * 2 + 1]);
        }
        __syncthreads();
        if (ck < 2) load_chunk(ck + 2, ck & 1);
    }

    // ---- epilogue: dequant + exp + label mask + row sums (registers) ----
    int lr0[4], lr1[4];
    float sr0[4], sr1[4];
    #pragma unroll
    for (int mi = 0; mi < 4; mi++) {
        int r = wy * 64 + mi * 16 + (l >> 2);
        lr0[mi] = labR[r];     sr0[mi] = scR[r];
        lr1[mi] = labR[r + 8]; sr1[mi] = scR[r + 8];
    }
    int lc0[4], lc1[4];
    float sc0[4], sc1[4];
    #pragma unroll
    for (int ni = 0; ni < 4; ni++) {
        int c = wx * 32 + ni * 8 + (l & 3) * 2;
        lc0[ni] = labC[c];     sc0[ni] = scC[c];
        lc1[ni] = labC[c + 1]; sc1[ni] = scC[c + 1];
    }

    float sLo[4], sHi[4];
    #pragma unroll
    for (int mi = 0; mi < 4; mi++) { sLo[mi] = 0.f; sHi[mi] = 0.f; }
    #pragma unroll
    for (int mi = 0; mi < 4; mi++)
        #pragma unroll
        for (int ni = 0; ni < 4; ni++) {
            float f00 = sr0[mi] * sc0[ni];
            float f01 = sr0[mi] * sc1[ni];
            float f10 = sr1[mi] * sc0[ni];
            float f11 = sr1[mi] * sc1[ni];
            float e0 = ex2f(__int2float_rn(acc[mi][ni][0]) * f00);
            float e1 = ex2f(__int2float_rn(acc[mi][ni][1]) * f01);
            float e2 = ex2f(__int2float_rn(acc[mi][ni][2]) * f10);
            float e3 = ex2f(__int2float_rn(acc[mi][ni][3]) * f11);
            sLo[mi] += (lr0[mi] != lc0[ni]) ? e0 : 0.f;
            sLo[mi] += (lr0[mi] != lc1[ni]) ? e1 : 0.f;
            sHi[mi] += (lr1[mi] != lc0[ni]) ? e2 : 0.f;
            sHi[mi] += (lr1[mi] != lc1[ni]) ? e3 : 0.f;
        }
    #pragma unroll
    for (int mi = 0; mi < 4; mi++) {
        sLo[mi] += __shfl_xor_sync(0xffffffffu, sLo[mi], 1);
        sLo[mi] += __shfl_xor_sync(0xffffffffu, sLo[mi], 2);
        sHi[mi] += __shfl_xor_sync(0xffffffffu, sHi[mi], 1);
        sHi[mi] += __shfl_xor_sync(0xffffffffu, sHi[mi], 2);
    }
    if ((l & 3) == 0) {
        int q = l >> 2;
        #pragma unroll
        for (int mi = 0; mi < 4; mi++) {
            red[wx][wy * 64 + mi * 16 + q]     = sLo[mi];
            red[wx][wy * 64 + mi * 16 + q + 8] = sHi[mi];
        }
    }
    __syncthreads();
    if (tid < 128) {
        float s = red[0][tid] + red[1][tid] + red[2][tid] + red[3][tid];
        g_negpart[(size_t)(rowBase + tid) * CT + blockIdx.x] = s;
    }
}

// ---------------------------------------------------------------
// Kernel 3: per-row finalize (sum 128 partials, diag - log) + block partials.
// ---------------------------------------------------------------
__global__ void k_rowfinal() {
    int idx = blockIdx.x * 256 + threadIdx.x;
    const float4* p = (const float4*)(g_negpart + (size_t)idx * CT);
    float ns = 0.f;
    #pragma unroll
    for (int i = 0; i < CT / 4; i++) {
        float4 v = p[i];
        ns += (v.x + v.y) + (v.z + v.w);
    }
    float val = g_diag[idx] - logf(ns);
    #pragma unroll
    for (int o = 16; o; o >>= 1) val += __shfl_xor_sync(0xffffffffu, val, o);
    __shared__ float sw[8];
    if ((threadIdx.x & 31) == 0) sw[threadIdx.x >> 5] = val;
    __syncthreads();
    if (threadIdx.x == 0) {
        float s = 0.f;
        #pragma unroll
        for (int i = 0; i < 8; i++) s += sw[i];
        g_partial[blockIdx.x] = s;
    }
}

// Kernel 4: final scalar
__global__ void k_final(float* __restrict__ out) {
    float v = g_partial[threadIdx.x];  // 64 threads
    #pragma unroll
    for (int o = 16; o; o >>= 1) v += __shfl_xor_sync(0xffffffffu, v, o);
    __shared__ float sw[2];
    if ((threadIdx.x & 31) == 0) sw[threadIdx.x >> 5] = v;
    __syncthreads();
    if (threadIdx.x == 0) out[0] = -(sw[0] + sw[1]) / (float)NB;
}

// ---------------------------------------------------------------
extern "C" void kernel_launch(void* const* d_in, const int* in_sizes, int n_in,
                              void* d_out, int out_size) {
    (void)in_sizes; (void)n_in; (void)out_size;
    const float* T   = (const float*)d_in[0];
    const float* S   = (const float*)d_in[1];
    const int*   lab = (const int*)d_in[2];
    float* out = (float*)d_out;

    k_norm<<<NB, 256>>>(T, S, lab);
    dim3 grid(CT, NB / TM);
    k_gemm<<<grid, 256>>>();
    k_rowfinal<<<64, 256>>>();
    k_final<<<1, 64>>>(out);
}